// round 1
// baseline (speedup 1.0000x reference)
#include <cuda_runtime.h>
#include <math.h>

// Shapes (fixed for this problem)
#define B_  8
#define L_  1024
#define E_  512
#define H_  8
#define D_  64
#define BH_ 64
#define M_  8192   // B*L

// Scratch (allowed: __device__ globals, no runtime alloc)
__device__ float g_h [M_ * E_];            // 16 MB  layernorm output [m, e]
__device__ float g_q [BH_ * L_ * D_];      // 16 MB  [bh, l, d]
__device__ float g_k [BH_ * L_ * D_];      // 16 MB  (pre-scaled by 1/sqrt(D))
__device__ float g_v [BH_ * L_ * D_];      // 16 MB
__device__ float g_S [67108864];           // 256 MB scores / probs [bh, l, m]
__device__ float g_ao[BH_ * L_ * D_];      // 16 MB  attention output [bh, l, d]

// ---------------------------------------------------------------- LayerNorm
__global__ __launch_bounds__(128) void ln_kernel(const float* __restrict__ x,
                                                 const float* __restrict__ gamma,
                                                 const float* __restrict__ beta) {
    int row = blockIdx.x;                       // 0..8191
    const float* xr = x + (size_t)row * E_;
    float* hr = g_h + (size_t)row * E_;
    int t = threadIdx.x;
    float v[4];
    float s = 0.f, sq = 0.f;
#pragma unroll
    for (int i = 0; i < 4; i++) {
        v[i] = xr[t + 128 * i];
        s += v[i];
        sq += v[i] * v[i];
    }
    __shared__ float sh[8];
#pragma unroll
    for (int o = 16; o > 0; o >>= 1) {
        s  += __shfl_xor_sync(0xffffffffu, s, o);
        sq += __shfl_xor_sync(0xffffffffu, sq, o);
    }
    int w = t >> 5;
    if ((t & 31) == 0) { sh[w] = s; sh[4 + w] = sq; }
    __syncthreads();
    if (t == 0) {
        float S  = sh[0] + sh[1] + sh[2] + sh[3];
        float SQ = sh[4] + sh[5] + sh[6] + sh[7];
        float mu  = S / 512.f;
        float var = SQ / 512.f - mu * mu;
        sh[0] = mu;
        sh[1] = rsqrtf(var + 1e-5f);
    }
    __syncthreads();
    float mu = sh[0], rs = sh[1];
#pragma unroll
    for (int i = 0; i < 4; i++) {
        int c = t + 128 * i;
        hr[c] = (v[i] - mu) * rs * gamma[c] + beta[c];
    }
}

// ------------------------------------------------- QKV projection (fused GEMM)
// y[m,n] = sum_k h[m,k] * W[n,k] + b[n];  K output pre-scaled by D^-0.5.
// Output scattered to head-major [bh, l, d].
__global__ __launch_bounds__(256) void qkv_kernel(const float* __restrict__ Wq,
                                                  const float* __restrict__ bq,
                                                  const float* __restrict__ Wk,
                                                  const float* __restrict__ bk,
                                                  const float* __restrict__ Wv,
                                                  const float* __restrict__ bv) {
    __shared__ float As[64][17];
    __shared__ float Bs[64][17];
    int nt = blockIdx.x;                 // 0..23  (1536 cols total)
    int mt = blockIdx.y;                 // 0..127
    int n0 = nt * 64;
    int which = n0 / 512;                // 0=q 1=k 2=v
    int nin = n0 % 512;
    const float* W    = (which == 0) ? Wq : (which == 1) ? Wk : Wv;
    const float* bias = (which == 0) ? bq : (which == 1) ? bk : bv;
    float* out        = (which == 0) ? g_q : (which == 1) ? g_k : g_v;
    float scale = (which == 1) ? rsqrtf(64.f) : 1.0f;

    int tid = threadIdx.x;
    int tx = tid & 15, ty = tid >> 4;
    float acc[4][4] = {};
    for (int k0 = 0; k0 < E_; k0 += 16) {
        for (int idx = tid; idx < 64 * 16; idx += 256) {
            int r = idx >> 4, c = idx & 15;
            As[r][c] = g_h[(size_t)(mt * 64 + r) * E_ + k0 + c];
        }
        for (int idx = tid; idx < 64 * 16; idx += 256) {
            int r = idx >> 4, c = idx & 15;
            Bs[r][c] = W[(size_t)(nin + r) * E_ + k0 + c];
        }
        __syncthreads();
#pragma unroll
        for (int kk = 0; kk < 16; kk++) {
            float a[4], b[4];
#pragma unroll
            for (int i = 0; i < 4; i++) a[i] = As[ty * 4 + i][kk];
#pragma unroll
            for (int j = 0; j < 4; j++) b[j] = Bs[tx * 4 + j][kk];
#pragma unroll
            for (int i = 0; i < 4; i++)
#pragma unroll
                for (int j = 0; j < 4; j++) acc[i][j] += a[i] * b[j];
        }
        __syncthreads();
    }
#pragma unroll
    for (int i = 0; i < 4; i++) {
        int m = mt * 64 + ty * 4 + i;
        int bb = m >> 10, l = m & 1023;
#pragma unroll
        for (int j = 0; j < 4; j++) {
            int n = nin + tx * 4 + j;
            int hh = n >> 6, d = n & 63;
            out[(size_t)((bb * 8 + hh) * 1024 + l) * 64 + d] =
                (acc[i][j] + bias[n]) * scale;
        }
    }
}

// ---------------------------------------------------- S = Q K^T (k pre-scaled)
__global__ __launch_bounds__(256) void qk_kernel() {
    if (blockIdx.x > blockIdx.y) return;   // causal tile skip
    int m0 = blockIdx.x * 64, l0 = blockIdx.y * 64, bh = blockIdx.z;
    __shared__ float Qs[64][65];
    __shared__ float Ks[64][65];
    const float* qb = g_q + (size_t)bh * 65536;
    const float* kb = g_k + (size_t)bh * 65536;
    int tid = threadIdx.x, tx = tid & 15, ty = tid >> 4;
    for (int idx = tid; idx < 4096; idx += 256) {
        int r = idx >> 6, c = idx & 63;
        Qs[r][c] = qb[(size_t)(l0 + r) * 64 + c];
        Ks[r][c] = kb[(size_t)(m0 + r) * 64 + c];
    }
    __syncthreads();
    float acc[4][4] = {};
#pragma unroll
    for (int kk = 0; kk < 64; kk++) {
        float a[4], b[4];
#pragma unroll
        for (int i = 0; i < 4; i++) a[i] = Qs[ty * 4 + i][kk];
#pragma unroll
        for (int j = 0; j < 4; j++) b[j] = Ks[tx * 4 + j][kk];
#pragma unroll
        for (int i = 0; i < 4; i++)
#pragma unroll
            for (int j = 0; j < 4; j++) acc[i][j] += a[i] * b[j];
    }
    float* Sb = g_S + ((size_t)bh << 20);
#pragma unroll
    for (int i = 0; i < 4; i++) {
        float4 vv = make_float4(acc[i][0], acc[i][1], acc[i][2], acc[i][3]);
        *(float4*)&Sb[(size_t)(l0 + ty * 4 + i) * 1024 + m0 + tx * 4] = vv;
    }
}

// ---------------------------- S += rel;  rel[l,m] = q_l . Er[h, m-l+1023, :]
__global__ __launch_bounds__(256) void rel_kernel(const float* __restrict__ Er) {
    if (blockIdx.x > blockIdx.y) return;
    int m0 = blockIdx.x * 64, l0 = blockIdx.y * 64, bh = blockIdx.z;
    int hh = bh & 7;
    __shared__ float Qs[64][64];        // 16 KB
    __shared__ float Es[64][127];       // 32.5 KB  [kk][band_row]
    const float* qb = g_q + (size_t)bh * 65536;
    const float* eb = Er + (size_t)hh * 1024 * 64;
    int r_base = m0 - l0 + 960;         // global Er row of band idx 0
    int tid = threadIdx.x, tx = tid & 15, ty = tid >> 4;
    for (int idx = tid; idx < 4096; idx += 256) {
        int r = idx >> 6, c = idx & 63;
        Qs[r][c] = qb[(size_t)(l0 + r) * 64 + c];
    }
    for (int idx = tid; idx < 64 * 127; idx += 256) {
        int kk = idx / 127, rr = idx % 127;
        int rg = r_base + rr;
        if (rg > 1023) rg = 1023;       // clamped rows are masked later
        Es[kk][rr] = eb[(size_t)rg * 64 + kk];
    }
    __syncthreads();
    float acc[4][4] = {};
#pragma unroll
    for (int kk = 0; kk < 64; kk++) {
        float a[4];
#pragma unroll
        for (int i = 0; i < 4; i++) a[i] = Qs[ty * 4 + i][kk];
#pragma unroll
        for (int i = 0; i < 4; i++) {
            int base = tx * 4 - (ty * 4 + i) + 63;
#pragma unroll
            for (int j = 0; j < 4; j++) acc[i][j] += a[i] * Es[kk][base + j];
        }
    }
    float* Sb = g_S + ((size_t)bh << 20);
#pragma unroll
    for (int i = 0; i < 4; i++) {
        float4* p = (float4*)&Sb[(size_t)(l0 + ty * 4 + i) * 1024 + m0 + tx * 4];
        float4 vv = *p;
        vv.x += acc[i][0]; vv.y += acc[i][1]; vv.z += acc[i][2]; vv.w += acc[i][3];
        *p = vv;
    }
}

// ------------------------------------------------------------ causal softmax
__global__ __launch_bounds__(128) void softmax_kernel() {
    int l = blockIdx.x, bh = blockIdx.y;
    float* row = g_S + ((size_t)bh << 20) + ((size_t)l << 10);
    int n = l + 1;
    int t = threadIdx.x;
    float vals[8];
    int cnt = 0;
    float mx = -1e30f;
    for (int i = t; i < n; i += 128) {
        float v = row[i];
        vals[cnt++] = v;
        mx = fmaxf(mx, v);
    }
    __shared__ float shm[4], shs[4], bc[2];
#pragma unroll
    for (int o = 16; o > 0; o >>= 1) mx = fmaxf(mx, __shfl_xor_sync(0xffffffffu, mx, o));
    if ((t & 31) == 0) shm[t >> 5] = mx;
    __syncthreads();
    float MX = fmaxf(fmaxf(shm[0], shm[1]), fmaxf(shm[2], shm[3]));
    float sum = 0.f;
    for (int j = 0; j < cnt; j++) {
        vals[j] = __expf(vals[j] - MX);
        sum += vals[j];
    }
#pragma unroll
    for (int o = 16; o > 0; o >>= 1) sum += __shfl_xor_sync(0xffffffffu, sum, o);
    if ((t & 31) == 0) shs[t >> 5] = sum;
    __syncthreads();
    if (t == 0) bc[0] = 1.f / (shs[0] + shs[1] + shs[2] + shs[3]);
    __syncthreads();
    float inv = bc[0];
    cnt = 0;
    for (int i = t; i < n; i += 128) row[i] = vals[cnt++] * inv;
}

// --------------------------------------------------------------- out = P @ V
__global__ __launch_bounds__(256) void pv_kernel() {
    int lt = blockIdx.y, bh = blockIdx.z;
    int l0 = lt * 64;
    __shared__ float Ps[64][65];
    __shared__ float Vs[64][65];
    const float* Sb = g_S + ((size_t)bh << 20);
    const float* vb = g_v + (size_t)bh * 65536;
    int tid = threadIdx.x, tx = tid & 15, ty = tid >> 4;
    float acc[4][4] = {};
    for (int kt = 0; kt <= lt; kt++) {
        for (int idx = tid; idx < 4096; idx += 256) {
            int r = idx >> 6, c = idx & 63;
            int mg = kt * 64 + c, lg = l0 + r;
            Ps[r][c] = (mg <= lg) ? Sb[(size_t)lg * 1024 + mg] : 0.f;
            Vs[r][c] = vb[(size_t)(kt * 64 + r) * 64 + c];
        }
        __syncthreads();
#pragma unroll
        for (int kk = 0; kk < 64; kk++) {
            float a[4], b[4];
#pragma unroll
            for (int i = 0; i < 4; i++) a[i] = Ps[ty * 4 + i][kk];
#pragma unroll
            for (int j = 0; j < 4; j++) b[j] = Vs[kk][tx * 4 + j];
#pragma unroll
            for (int i = 0; i < 4; i++)
#pragma unroll
                for (int j = 0; j < 4; j++) acc[i][j] += a[i] * b[j];
        }
        __syncthreads();
    }
    float* ob = g_ao + (size_t)bh * 65536;
#pragma unroll
    for (int i = 0; i < 4; i++) {
        float4 vv = make_float4(acc[i][0], acc[i][1], acc[i][2], acc[i][3]);
        *(float4*)&ob[(size_t)(l0 + ty * 4 + i) * 64 + tx * 4] = vv;
    }
}

// -------------------------------------------------- output projection + bias
__global__ __launch_bounds__(256) void oproj_kernel(const float* __restrict__ Wo,
                                                    const float* __restrict__ bo,
                                                    float* __restrict__ out) {
    __shared__ float As[64][17];
    __shared__ float Bs[64][17];
    int nt = blockIdx.x;                 // 0..7
    int mt = blockIdx.y;                 // 0..127
    int n0 = nt * 64;
    int tid = threadIdx.x, tx = tid & 15, ty = tid >> 4;
    float acc[4][4] = {};
    for (int k0 = 0; k0 < E_; k0 += 16) {
        for (int idx = tid; idx < 64 * 16; idx += 256) {
            int r = idx >> 4, c = idx & 15;
            int m = mt * 64 + r, e = k0 + c;
            // A[m,e] gather from head-major attn output
            As[r][c] = g_ao[(size_t)(((m >> 10) * 8 + (e >> 6)) * 1024 + (m & 1023)) * 64 + (e & 63)];
        }
        for (int idx = tid; idx < 64 * 16; idx += 256) {
            int r = idx >> 4, c = idx & 15;
            Bs[r][c] = Wo[(size_t)(n0 + r) * E_ + k0 + c];
        }
        __syncthreads();
#pragma unroll
        for (int kk = 0; kk < 16; kk++) {
            float a[4], b[4];
#pragma unroll
            for (int i = 0; i < 4; i++) a[i] = As[ty * 4 + i][kk];
#pragma unroll
            for (int j = 0; j < 4; j++) b[j] = Bs[tx * 4 + j][kk];
#pragma unroll
            for (int i = 0; i < 4; i++)
#pragma unroll
                for (int j = 0; j < 4; j++) acc[i][j] += a[i] * b[j];
        }
        __syncthreads();
    }
#pragma unroll
    for (int i = 0; i < 4; i++) {
        int m = mt * 64 + ty * 4 + i;
#pragma unroll
        for (int j = 0; j < 4; j++) {
            int n = n0 + tx * 4 + j;
            out[(size_t)m * 512 + n] = acc[i][j] + bo[n];
        }
    }
}

// ----------------------------------------------------------------- launcher
extern "C" void kernel_launch(void* const* d_in, const int* in_sizes, int n_in,
                              void* d_out, int out_size) {
    const float* x     = (const float*)d_in[0];
    // d_in[1] = mask (causal triu, known statically -> ignored)
    const float* gamma = (const float*)d_in[2];
    const float* beta  = (const float*)d_in[3];
    const float* Wq    = (const float*)d_in[4];
    const float* bq    = (const float*)d_in[5];
    const float* Wk    = (const float*)d_in[6];
    const float* bk    = (const float*)d_in[7];
    const float* Wv    = (const float*)d_in[8];
    const float* bv    = (const float*)d_in[9];
    const float* Wo    = (const float*)d_in[10];
    const float* bo    = (const float*)d_in[11];
    const float* Er    = (const float*)d_in[12];
    float* out = (float*)d_out;

    ln_kernel<<<M_, 128>>>(x, gamma, beta);
    qkv_kernel<<<dim3(24, 128), 256>>>(Wq, bq, Wk, bk, Wv, bv);
    qk_kernel<<<dim3(16, 16, BH_), 256>>>();
    rel_kernel<<<dim3(16, 16, BH_), 256>>>(Er);
    softmax_kernel<<<dim3(L_, BH_), 128>>>();
    pv_kernel<<<dim3(1, 16, BH_), 256>>>();
    oproj_kernel<<<dim3(8, 128), 256>>>(Wo, bo, out);
}

// round 2
// speedup vs baseline: 1.0000x; 1.0000x over previous
#include <cuda_runtime.h>
#include <math.h>

// Shapes (fixed for this problem)
#define B_  8
#define L_  1024
#define E_  512
#define H_  8
#define D_  64
#define BH_ 64
#define M_  8192   // B*L

// Scratch (allowed: __device__ globals, no runtime alloc)
__device__ float g_h [M_ * E_];            // 16 MB  layernorm output [m, e]
__device__ float g_q [BH_ * L_ * D_];      // 16 MB  [bh, l, d]
__device__ float g_k [BH_ * L_ * D_];      // 16 MB  (pre-scaled by 1/sqrt(D))
__device__ float g_v [BH_ * L_ * D_];      // 16 MB
__device__ float g_S [67108864];           // 256 MB scores / probs [bh, l, m]
__device__ float g_ao[BH_ * L_ * D_];      // 16 MB  attention output [bh, l, d]

// ---------------------------------------------------------------- LayerNorm
__global__ __launch_bounds__(128) void ln_kernel(const float* __restrict__ x,
                                                 const float* __restrict__ gamma,
                                                 const float* __restrict__ beta) {
    int row = blockIdx.x;                       // 0..8191
    const float* xr = x + (size_t)row * E_;
    float* hr = g_h + (size_t)row * E_;
    int t = threadIdx.x;
    float v[4];
    float s = 0.f, sq = 0.f;
#pragma unroll
    for (int i = 0; i < 4; i++) {
        v[i] = xr[t + 128 * i];
        s += v[i];
        sq += v[i] * v[i];
    }
    __shared__ float sh[8];
#pragma unroll
    for (int o = 16; o > 0; o >>= 1) {
        s  += __shfl_xor_sync(0xffffffffu, s, o);
        sq += __shfl_xor_sync(0xffffffffu, sq, o);
    }
    int w = t >> 5;
    if ((t & 31) == 0) { sh[w] = s; sh[4 + w] = sq; }
    __syncthreads();
    if (t == 0) {
        float S  = sh[0] + sh[1] + sh[2] + sh[3];
        float SQ = sh[4] + sh[5] + sh[6] + sh[7];
        float mu  = S / 512.f;
        float var = SQ / 512.f - mu * mu;
        sh[0] = mu;
        sh[1] = rsqrtf(var + 1e-5f);
    }
    __syncthreads();
    float mu = sh[0], rs = sh[1];
#pragma unroll
    for (int i = 0; i < 4; i++) {
        int c = t + 128 * i;
        hr[c] = (v[i] - mu) * rs * gamma[c] + beta[c];
    }
}

// ------------------------------------------------- QKV projection (fused GEMM)
// y[m,n] = sum_k h[m,k] * W[n,k] + b[n];  K output pre-scaled by D^-0.5.
// Output scattered to head-major [bh, l, d].
__global__ __launch_bounds__(256) void qkv_kernel(const float* __restrict__ Wq,
                                                  const float* __restrict__ bq,
                                                  const float* __restrict__ Wk,
                                                  const float* __restrict__ bk,
                                                  const float* __restrict__ Wv,
                                                  const float* __restrict__ bv) {
    __shared__ float As[64][17];
    __shared__ float Bs[64][17];
    int nt = blockIdx.x;                 // 0..23  (1536 cols total)
    int mt = blockIdx.y;                 // 0..127
    int n0 = nt * 64;
    int which = n0 / 512;                // 0=q 1=k 2=v
    int nin = n0 % 512;
    const float* W    = (which == 0) ? Wq : (which == 1) ? Wk : Wv;
    const float* bias = (which == 0) ? bq : (which == 1) ? bk : bv;
    float* out        = (which == 0) ? g_q : (which == 1) ? g_k : g_v;
    float scale = (which == 1) ? rsqrtf(64.f) : 1.0f;

    int tid = threadIdx.x;
    int tx = tid & 15, ty = tid >> 4;
    float acc[4][4] = {};
    for (int k0 = 0; k0 < E_; k0 += 16) {
        for (int idx = tid; idx < 64 * 16; idx += 256) {
            int r = idx >> 4, c = idx & 15;
            As[r][c] = g_h[(size_t)(mt * 64 + r) * E_ + k0 + c];
        }
        for (int idx = tid; idx < 64 * 16; idx += 256) {
            int r = idx >> 4, c = idx & 15;
            Bs[r][c] = W[(size_t)(nin + r) * E_ + k0 + c];
        }
        __syncthreads();
#pragma unroll
        for (int kk = 0; kk < 16; kk++) {
            float a[4], b[4];
#pragma unroll
            for (int i = 0; i < 4; i++) a[i] = As[ty * 4 + i][kk];
#pragma unroll
            for (int j = 0; j < 4; j++) b[j] = Bs[tx * 4 + j][kk];
#pragma unroll
            for (int i = 0; i < 4; i++)
#pragma unroll
                for (int j = 0; j < 4; j++) acc[i][j] += a[i] * b[j];
        }
        __syncthreads();
    }
#pragma unroll
    for (int i = 0; i < 4; i++) {
        int m = mt * 64 + ty * 4 + i;
        int bb = m >> 10, l = m & 1023;
#pragma unroll
        for (int j = 0; j < 4; j++) {
            int n = nin + tx * 4 + j;
            int hh = n >> 6, d = n & 63;
            out[(size_t)((bb * 8 + hh) * 1024 + l) * 64 + d] =
                (acc[i][j] + bias[n]) * scale;
        }
    }
}

// ---------------------------------------------------- S = Q K^T (k pre-scaled)
__global__ __launch_bounds__(256) void qk_kernel() {
    if (blockIdx.x > blockIdx.y) return;   // causal tile skip
    int m0 = blockIdx.x * 64, l0 = blockIdx.y * 64, bh = blockIdx.z;
    __shared__ float Qs[64][65];
    __shared__ float Ks[64][65];
    const float* qb = g_q + (size_t)bh * 65536;
    const float* kb = g_k + (size_t)bh * 65536;
    int tid = threadIdx.x, tx = tid & 15, ty = tid >> 4;
    for (int idx = tid; idx < 4096; idx += 256) {
        int r = idx >> 6, c = idx & 63;
        Qs[r][c] = qb[(size_t)(l0 + r) * 64 + c];
        Ks[r][c] = kb[(size_t)(m0 + r) * 64 + c];
    }
    __syncthreads();
    float acc[4][4] = {};
#pragma unroll
    for (int kk = 0; kk < 64; kk++) {
        float a[4], b[4];
#pragma unroll
        for (int i = 0; i < 4; i++) a[i] = Qs[ty * 4 + i][kk];
#pragma unroll
        for (int j = 0; j < 4; j++) b[j] = Ks[tx * 4 + j][kk];
#pragma unroll
        for (int i = 0; i < 4; i++)
#pragma unroll
            for (int j = 0; j < 4; j++) acc[i][j] += a[i] * b[j];
    }
    float* Sb = g_S + ((size_t)bh << 20);
#pragma unroll
    for (int i = 0; i < 4; i++) {
        float4 vv = make_float4(acc[i][0], acc[i][1], acc[i][2], acc[i][3]);
        *(float4*)&Sb[(size_t)(l0 + ty * 4 + i) * 1024 + m0 + tx * 4] = vv;
    }
}

// ---------------------------- S += rel;  rel[l,m] = q_l . Er[h, m-l+1023, :]
__global__ __launch_bounds__(256) void rel_kernel(const float* __restrict__ Er) {
    if (blockIdx.x > blockIdx.y) return;
    int m0 = blockIdx.x * 64, l0 = blockIdx.y * 64, bh = blockIdx.z;
    int hh = bh & 7;
    __shared__ float Qs[64][64];        // 16 KB
    __shared__ float Es[64][127];       // 32.5 KB  [kk][band_row]
    const float* qb = g_q + (size_t)bh * 65536;
    const float* eb = Er + (size_t)hh * 1024 * 64;
    int r_base = m0 - l0 + 960;         // global Er row of band idx 0
    int tid = threadIdx.x, tx = tid & 15, ty = tid >> 4;
    for (int idx = tid; idx < 4096; idx += 256) {
        int r = idx >> 6, c = idx & 63;
        Qs[r][c] = qb[(size_t)(l0 + r) * 64 + c];
    }
    for (int idx = tid; idx < 64 * 127; idx += 256) {
        int kk = idx / 127, rr = idx % 127;
        int rg = r_base + rr;
        if (rg > 1023) rg = 1023;       // clamped rows are masked later
        Es[kk][rr] = eb[(size_t)rg * 64 + kk];
    }
    __syncthreads();
    float acc[4][4] = {};
#pragma unroll
    for (int kk = 0; kk < 64; kk++) {
        float a[4];
#pragma unroll
        for (int i = 0; i < 4; i++) a[i] = Qs[ty * 4 + i][kk];
#pragma unroll
        for (int i = 0; i < 4; i++) {
            int base = tx * 4 - (ty * 4 + i) + 63;
#pragma unroll
            for (int j = 0; j < 4; j++) acc[i][j] += a[i] * Es[kk][base + j];
        }
    }
    float* Sb = g_S + ((size_t)bh << 20);
#pragma unroll
    for (int i = 0; i < 4; i++) {
        float4* p = (float4*)&Sb[(size_t)(l0 + ty * 4 + i) * 1024 + m0 + tx * 4];
        float4 vv = *p;
        vv.x += acc[i][0]; vv.y += acc[i][1]; vv.z += acc[i][2]; vv.w += acc[i][3];
        *p = vv;
    }
}

// ------------------------------------------------------------ causal softmax
__global__ __launch_bounds__(128) void softmax_kernel() {
    int l = blockIdx.x, bh = blockIdx.y;
    float* row = g_S + ((size_t)bh << 20) + ((size_t)l << 10);
    int n = l + 1;
    int t = threadIdx.x;
    float vals[8];
    int cnt = 0;
    float mx = -1e30f;
    for (int i = t; i < n; i += 128) {
        float v = row[i];
        vals[cnt++] = v;
        mx = fmaxf(mx, v);
    }
    __shared__ float shm[4], shs[4], bc[2];
#pragma unroll
    for (int o = 16; o > 0; o >>= 1) mx = fmaxf(mx, __shfl_xor_sync(0xffffffffu, mx, o));
    if ((t & 31) == 0) shm[t >> 5] = mx;
    __syncthreads();
    float MX = fmaxf(fmaxf(shm[0], shm[1]), fmaxf(shm[2], shm[3]));
    float sum = 0.f;
    for (int j = 0; j < cnt; j++) {
        vals[j] = __expf(vals[j] - MX);
        sum += vals[j];
    }
#pragma unroll
    for (int o = 16; o > 0; o >>= 1) sum += __shfl_xor_sync(0xffffffffu, sum, o);
    if ((t & 31) == 0) shs[t >> 5] = sum;
    __syncthreads();
    if (t == 0) bc[0] = 1.f / (shs[0] + shs[1] + shs[2] + shs[3]);
    __syncthreads();
    float inv = bc[0];
    cnt = 0;
    for (int i = t; i < n; i += 128) row[i] = vals[cnt++] * inv;
}

// --------------------------------------------------------------- out = P @ V
__global__ __launch_bounds__(256) void pv_kernel() {
    int lt = blockIdx.y, bh = blockIdx.z;
    int l0 = lt * 64;
    __shared__ float Ps[64][65];
    __shared__ float Vs[64][65];
    const float* Sb = g_S + ((size_t)bh << 20);
    const float* vb = g_v + (size_t)bh * 65536;
    int tid = threadIdx.x, tx = tid & 15, ty = tid >> 4;
    float acc[4][4] = {};
    for (int kt = 0; kt <= lt; kt++) {
        for (int idx = tid; idx < 4096; idx += 256) {
            int r = idx >> 6, c = idx & 63;
            int mg = kt * 64 + c, lg = l0 + r;
            Ps[r][c] = (mg <= lg) ? Sb[(size_t)lg * 1024 + mg] : 0.f;
            Vs[r][c] = vb[(size_t)(kt * 64 + r) * 64 + c];
        }
        __syncthreads();
#pragma unroll
        for (int kk = 0; kk < 64; kk++) {
            float a[4], b[4];
#pragma unroll
            for (int i = 0; i < 4; i++) a[i] = Ps[ty * 4 + i][kk];
#pragma unroll
            for (int j = 0; j < 4; j++) b[j] = Vs[kk][tx * 4 + j];
#pragma unroll
            for (int i = 0; i < 4; i++)
#pragma unroll
                for (int j = 0; j < 4; j++) acc[i][j] += a[i] * b[j];
        }
        __syncthreads();
    }
    float* ob = g_ao + (size_t)bh * 65536;
#pragma unroll
    for (int i = 0; i < 4; i++) {
        float4 vv = make_float4(acc[i][0], acc[i][1], acc[i][2], acc[i][3]);
        *(float4*)&ob[(size_t)(l0 + ty * 4 + i) * 64 + tx * 4] = vv;
    }
}

// -------------------------------------------------- output projection + bias
__global__ __launch_bounds__(256) void oproj_kernel(const float* __restrict__ Wo,
                                                    const float* __restrict__ bo,
                                                    float* __restrict__ out) {
    __shared__ float As[64][17];
    __shared__ float Bs[64][17];
    int nt = blockIdx.x;                 // 0..7
    int mt = blockIdx.y;                 // 0..127
    int n0 = nt * 64;
    int tid = threadIdx.x, tx = tid & 15, ty = tid >> 4;
    float acc[4][4] = {};
    for (int k0 = 0; k0 < E_; k0 += 16) {
        for (int idx = tid; idx < 64 * 16; idx += 256) {
            int r = idx >> 4, c = idx & 15;
            int m = mt * 64 + r, e = k0 + c;
            // A[m,e] gather from head-major attn output
            As[r][c] = g_ao[(size_t)(((m >> 10) * 8 + (e >> 6)) * 1024 + (m & 1023)) * 64 + (e & 63)];
        }
        for (int idx = tid; idx < 64 * 16; idx += 256) {
            int r = idx >> 4, c = idx & 15;
            Bs[r][c] = Wo[(size_t)(n0 + r) * E_ + k0 + c];
        }
        __syncthreads();
#pragma unroll
        for (int kk = 0; kk < 16; kk++) {
            float a[4], b[4];
#pragma unroll
            for (int i = 0; i < 4; i++) a[i] = As[ty * 4 + i][kk];
#pragma unroll
            for (int j = 0; j < 4; j++) b[j] = Bs[tx * 4 + j][kk];
#pragma unroll
            for (int i = 0; i < 4; i++)
#pragma unroll
                for (int j = 0; j < 4; j++) acc[i][j] += a[i] * b[j];
        }
        __syncthreads();
    }
#pragma unroll
    for (int i = 0; i < 4; i++) {
        int m = mt * 64 + ty * 4 + i;
#pragma unroll
        for (int j = 0; j < 4; j++) {
            int n = n0 + tx * 4 + j;
            out[(size_t)m * 512 + n] = acc[i][j] + bo[n];
        }
    }
}

// ----------------------------------------------------------------- launcher
extern "C" void kernel_launch(void* const* d_in, const int* in_sizes, int n_in,
                              void* d_out, int out_size) {
    const float* x     = (const float*)d_in[0];
    // d_in[1] = mask (causal triu, known statically -> ignored)
    const float* gamma = (const float*)d_in[2];
    const float* beta  = (const float*)d_in[3];
    const float* Wq    = (const float*)d_in[4];
    const float* bq    = (const float*)d_in[5];
    const float* Wk    = (const float*)d_in[6];
    const float* bk    = (const float*)d_in[7];
    const float* Wv    = (const float*)d_in[8];
    const float* bv    = (const float*)d_in[9];
    const float* Wo    = (const float*)d_in[10];
    const float* bo    = (const float*)d_in[11];
    const float* Er    = (const float*)d_in[12];
    float* out = (float*)d_out;

    ln_kernel<<<M_, 128>>>(x, gamma, beta);
    qkv_kernel<<<dim3(24, 128), 256>>>(Wq, bq, Wk, bk, Wv, bv);
    qk_kernel<<<dim3(16, 16, BH_), 256>>>();
    rel_kernel<<<dim3(16, 16, BH_), 256>>>(Er);
    softmax_kernel<<<dim3(L_, BH_), 128>>>();
    pv_kernel<<<dim3(1, 16, BH_), 256>>>();
    oproj_kernel<<<dim3(8, 128), 256>>>(Wo, bo, out);
}

// round 3
// speedup vs baseline: 1.5650x; 1.5649x over previous
#include <cuda_runtime.h>
#include <math.h>

// Shapes (fixed)
#define B_  8
#define L_  1024
#define E_  512
#define H_  8
#define D_  64
#define BH_ 64
#define M_  8192   // B*L

// Scratch (__device__ globals; no runtime alloc)
__device__ float g_h [M_ * E_];            // 16 MB  layernorm out [m, e]
__device__ float g_q [BH_ * L_ * D_];      // 16 MB  [bh, l, d]
__device__ float g_k [BH_ * L_ * D_];      // 16 MB  (pre-scaled by D^-0.5)
__device__ float g_v [BH_ * L_ * D_];      // 16 MB
__device__ float g_S [67108864];           // 256 MB scores/probs [bh, l, m]
__device__ float g_R [67108864];           // 256 MB rel logits    [bh, l, r]
__device__ float g_ao[BH_ * L_ * D_];      // 16 MB  attn out [bh, l, d]

// ---------------------------------------------------------------- LayerNorm
__global__ __launch_bounds__(128) void ln_kernel(const float* __restrict__ x,
                                                 const float* __restrict__ gamma,
                                                 const float* __restrict__ beta) {
    int row = blockIdx.x;
    const float* xr = x + (size_t)row * E_;
    float* hr = g_h + (size_t)row * E_;
    int t = threadIdx.x;
    float v[4];
    float s = 0.f, sq = 0.f;
#pragma unroll
    for (int i = 0; i < 4; i++) {
        v[i] = xr[t + 128 * i];
        s += v[i];
        sq += v[i] * v[i];
    }
    __shared__ float sh[8];
#pragma unroll
    for (int o = 16; o > 0; o >>= 1) {
        s  += __shfl_xor_sync(0xffffffffu, s, o);
        sq += __shfl_xor_sync(0xffffffffu, sq, o);
    }
    int w = t >> 5;
    if ((t & 31) == 0) { sh[w] = s; sh[4 + w] = sq; }
    __syncthreads();
    if (t == 0) {
        float S  = sh[0] + sh[1] + sh[2] + sh[3];
        float SQ = sh[4] + sh[5] + sh[6] + sh[7];
        float mu  = S / 512.f;
        float var = SQ / 512.f - mu * mu;
        sh[0] = mu;
        sh[1] = rsqrtf(var + 1e-5f);
    }
    __syncthreads();
    float mu = sh[0], rs = sh[1];
#pragma unroll
    for (int i = 0; i < 4; i++) {
        int c = t + 128 * i;
        hr[c] = (v[i] - mu) * rs * gamma[c] + beta[c];
    }
}

// ------------------------------------------------- QKV projection (big GEMM)
// y[m,n] = sum_k h[m,k]*W[n,k] + b[n].  K output scaled by D^-0.5.
// 128x128 tile, 256 threads, 8x8 per thread. Scatter to head-major.
__global__ __launch_bounds__(256) void qkv_kernel(const float* __restrict__ Wq,
                                                  const float* __restrict__ bq,
                                                  const float* __restrict__ Wk,
                                                  const float* __restrict__ bk,
                                                  const float* __restrict__ Wv,
                                                  const float* __restrict__ bv) {
    __shared__ float As[16][132];
    __shared__ float Bs[16][132];
    int n0g = blockIdx.x * 128;          // 0..1535
    int m0  = blockIdx.y * 128;
    int which = n0g >> 9;                // 0=q 1=k 2=v
    int nin = n0g & 511;
    const float* W    = (which == 0) ? Wq : (which == 1) ? Wk : Wv;
    const float* bias = (which == 0) ? bq : (which == 1) ? bk : bv;
    float* out        = (which == 0) ? g_q : (which == 1) ? g_k : g_v;
    float scale = (which == 1) ? 0.125f : 1.0f;

    int tid = threadIdx.x;
    int tx = tid & 15, ty = tid >> 4;
    float acc[8][8] = {};
    for (int k0 = 0; k0 < E_; k0 += 16) {
#pragma unroll
        for (int it = 0; it < 8; it++) {
            int idx = tid + it * 256;
            int r = idx >> 4, c = idx & 15;
            As[c][r] = g_h[(size_t)(m0 + r) * E_ + k0 + c];
            Bs[c][r] = W[(size_t)(nin + r) * E_ + k0 + c];
        }
        __syncthreads();
#pragma unroll
        for (int kk = 0; kk < 16; kk++) {
            float a[8];
#pragma unroll
            for (int i = 0; i < 8; i++) a[i] = As[kk][ty * 8 + i];
            float4 b0 = *(const float4*)&Bs[kk][tx * 8];
            float4 b1 = *(const float4*)&Bs[kk][tx * 8 + 4];
            float b[8] = {b0.x, b0.y, b0.z, b0.w, b1.x, b1.y, b1.z, b1.w};
#pragma unroll
            for (int i = 0; i < 8; i++)
#pragma unroll
                for (int j = 0; j < 8; j++) acc[i][j] += a[i] * b[j];
        }
        __syncthreads();
    }
#pragma unroll
    for (int i = 0; i < 8; i++) {
        int m = m0 + ty * 8 + i;
        int bb = m >> 10, l = m & 1023;
#pragma unroll
        for (int j = 0; j < 8; j++) {
            int n = nin + tx * 8 + j;
            int hh = n >> 6, d = n & 63;
            out[(size_t)((bb * 8 + hh) * 1024 + l) * 64 + d] =
                (acc[i][j] + bias[n]) * scale;
        }
    }
}

// ---------------------------------------------------- S = Q K^T (k scaled)
__global__ __launch_bounds__(256) void qk_kernel() {
    int mi = blockIdx.x, li = blockIdx.y;
    if (mi > li) return;                 // causal tile skip
    int m0 = mi * 128, l0 = li * 128, bh = blockIdx.z;
    __shared__ float As[16][132];
    __shared__ float Bs[16][132];
    const float* qb = g_q + (size_t)bh * 65536;
    const float* kb = g_k + (size_t)bh * 65536;
    int tid = threadIdx.x, tx = tid & 15, ty = tid >> 4;
    float acc[8][8] = {};
    for (int k0 = 0; k0 < 64; k0 += 16) {
#pragma unroll
        for (int it = 0; it < 8; it++) {
            int idx = tid + it * 256;
            int r = idx >> 4, c = idx & 15;
            As[c][r] = qb[(size_t)(l0 + r) * 64 + k0 + c];
            Bs[c][r] = kb[(size_t)(m0 + r) * 64 + k0 + c];
        }
        __syncthreads();
#pragma unroll
        for (int kk = 0; kk < 16; kk++) {
            float a[8];
#pragma unroll
            for (int i = 0; i < 8; i++) a[i] = As[kk][ty * 8 + i];
            float4 b0 = *(const float4*)&Bs[kk][tx * 8];
            float4 b1 = *(const float4*)&Bs[kk][tx * 8 + 4];
            float b[8] = {b0.x, b0.y, b0.z, b0.w, b1.x, b1.y, b1.z, b1.w};
#pragma unroll
            for (int i = 0; i < 8; i++)
#pragma unroll
                for (int j = 0; j < 8; j++) acc[i][j] += a[i] * b[j];
        }
        __syncthreads();
    }
    float* Sb = g_S + ((size_t)bh << 20);
#pragma unroll
    for (int i = 0; i < 8; i++) {
        float* rowp = &Sb[(size_t)(l0 + ty * 8 + i) * 1024 + m0 + tx * 8];
        *(float4*)rowp       = make_float4(acc[i][0], acc[i][1], acc[i][2], acc[i][3]);
        *(float4*)(rowp + 4) = make_float4(acc[i][4], acc[i][5], acc[i][6], acc[i][7]);
    }
}

// ---------------------------------------- R[l,r] = q_l . Er[h, r, :]  (GEMM)
// Only tiles with l+r able to reach >= 1023 are needed: li+ri >= 7.
__global__ __launch_bounds__(256) void qer_kernel(const float* __restrict__ Er) {
    int ri = blockIdx.x, li = blockIdx.y;
    if (ri + li < 7) return;
    int r0 = ri * 128, l0 = li * 128, bh = blockIdx.z;
    int hh = bh & 7;
    __shared__ float As[16][132];
    __shared__ float Bs[16][132];
    const float* qb = g_q + (size_t)bh * 65536;
    const float* eb = Er + (size_t)hh * 65536;
    int tid = threadIdx.x, tx = tid & 15, ty = tid >> 4;
    float acc[8][8] = {};
    for (int k0 = 0; k0 < 64; k0 += 16) {
#pragma unroll
        for (int it = 0; it < 8; it++) {
            int idx = tid + it * 256;
            int r = idx >> 4, c = idx & 15;
            As[c][r] = qb[(size_t)(l0 + r) * 64 + k0 + c];
            Bs[c][r] = eb[(size_t)(r0 + r) * 64 + k0 + c];
        }
        __syncthreads();
#pragma unroll
        for (int kk = 0; kk < 16; kk++) {
            float a[8];
#pragma unroll
            for (int i = 0; i < 8; i++) a[i] = As[kk][ty * 8 + i];
            float4 b0 = *(const float4*)&Bs[kk][tx * 8];
            float4 b1 = *(const float4*)&Bs[kk][tx * 8 + 4];
            float b[8] = {b0.x, b0.y, b0.z, b0.w, b1.x, b1.y, b1.z, b1.w};
#pragma unroll
            for (int i = 0; i < 8; i++)
#pragma unroll
                for (int j = 0; j < 8; j++) acc[i][j] += a[i] * b[j];
        }
        __syncthreads();
    }
    float* Rb = g_R + ((size_t)bh << 20);
#pragma unroll
    for (int i = 0; i < 8; i++) {
        float* rowp = &Rb[(size_t)(l0 + ty * 8 + i) * 1024 + r0 + tx * 8];
        *(float4*)rowp       = make_float4(acc[i][0], acc[i][1], acc[i][2], acc[i][3]);
        *(float4*)(rowp + 4) = make_float4(acc[i][4], acc[i][5], acc[i][6], acc[i][7]);
    }
}

// --------------------------- causal softmax with fused rel gather-add
// P[l,m] = softmax_m<=l( S[l,m] + R[l, m+1023-l] )
__global__ __launch_bounds__(128) void softmax_kernel() {
    int l = blockIdx.x, bh = blockIdx.y;
    float* row        = g_S + ((size_t)bh << 20) + ((size_t)l << 10);
    const float* rrow = g_R + ((size_t)bh << 20) + ((size_t)l << 10) + (1023 - l);
    int n = l + 1;
    int t = threadIdx.x;
    float vals[8];
    int cnt = 0;
    float mx = -1e30f;
    for (int i = t; i < n; i += 128) {
        float v = row[i] + rrow[i];
        vals[cnt++] = v;
        mx = fmaxf(mx, v);
    }
    __shared__ float shm[4], shs[4], bc[1];
#pragma unroll
    for (int o = 16; o > 0; o >>= 1) mx = fmaxf(mx, __shfl_xor_sync(0xffffffffu, mx, o));
    if ((t & 31) == 0) shm[t >> 5] = mx;
    __syncthreads();
    float MX = fmaxf(fmaxf(shm[0], shm[1]), fmaxf(shm[2], shm[3]));
    float sum = 0.f;
    for (int j = 0; j < cnt; j++) {
        vals[j] = __expf(vals[j] - MX);
        sum += vals[j];
    }
#pragma unroll
    for (int o = 16; o > 0; o >>= 1) sum += __shfl_xor_sync(0xffffffffu, sum, o);
    if ((t & 31) == 0) shs[t >> 5] = sum;
    __syncthreads();
    if (t == 0) bc[0] = 1.f / (shs[0] + shs[1] + shs[2] + shs[3]);
    __syncthreads();
    float inv = bc[0];
    cnt = 0;
    for (int i = t; i < n; i += 128) row[i] = vals[cnt++] * inv;
}

// --------------------------------------------------------------- out = P @ V
// Tile 128(l) x 64(d), 128 threads, 8x8 per thread, K-chunks of 32.
__global__ __launch_bounds__(128) void pv_kernel() {
    int li = blockIdx.x, bh = blockIdx.y;
    int l0 = li * 128;
    __shared__ float Ps[32][132];
    __shared__ float Vs[32][68];
    const float* Sb = g_S + ((size_t)bh << 20);
    const float* vb = g_v + (size_t)bh * 65536;
    int tid = threadIdx.x, tx = tid & 7, ty = tid >> 3;   // 8 x 16
    float acc[8][8] = {};
    for (int kt = 0; kt <= li; kt++) {
        for (int ck = 0; ck < 4; ck++) {
            int kbase = kt * 128 + ck * 32;
#pragma unroll
            for (int it = 0; it < 32; it++) {
                int idx = tid + it * 128;
                int r = idx >> 5, c = idx & 31;   // r = l row, c = kk
                int mg = kbase + c, lg = l0 + r;
                Ps[c][r] = (mg <= lg) ? Sb[(size_t)lg * 1024 + mg] : 0.f;
            }
#pragma unroll
            for (int it = 0; it < 16; it++) {
                int idx = tid + it * 128;
                int r = idx >> 6, c = idx & 63;
                Vs[r][c] = vb[(size_t)(kbase + r) * 64 + c];
            }
            __syncthreads();
#pragma unroll
            for (int kk = 0; kk < 32; kk++) {
                float a[8];
#pragma unroll
                for (int i = 0; i < 8; i++) a[i] = Ps[kk][ty * 8 + i];
                float4 b0 = *(const float4*)&Vs[kk][tx * 8];
                float4 b1 = *(const float4*)&Vs[kk][tx * 8 + 4];
                float b[8] = {b0.x, b0.y, b0.z, b0.w, b1.x, b1.y, b1.z, b1.w};
#pragma unroll
                for (int i = 0; i < 8; i++)
#pragma unroll
                    for (int j = 0; j < 8; j++) acc[i][j] += a[i] * b[j];
            }
            __syncthreads();
        }
    }
    float* ob = g_ao + (size_t)bh * 65536;
#pragma unroll
    for (int i = 0; i < 8; i++) {
        float* rowp = &ob[(size_t)(l0 + ty * 8 + i) * 64 + tx * 8];
        *(float4*)rowp       = make_float4(acc[i][0], acc[i][1], acc[i][2], acc[i][3]);
        *(float4*)(rowp + 4) = make_float4(acc[i][4], acc[i][5], acc[i][6], acc[i][7]);
    }
}

// -------------------------------------------------- output projection + bias
__global__ __launch_bounds__(256) void oproj_kernel(const float* __restrict__ Wo,
                                                    const float* __restrict__ bo,
                                                    float* __restrict__ out) {
    __shared__ float As[16][132];
    __shared__ float Bs[16][132];
    int n0 = blockIdx.x * 128;
    int m0 = blockIdx.y * 128;
    int tid = threadIdx.x, tx = tid & 15, ty = tid >> 4;
    float acc[8][8] = {};
    for (int k0 = 0; k0 < E_; k0 += 16) {
#pragma unroll
        for (int it = 0; it < 8; it++) {
            int idx = tid + it * 256;
            int r = idx >> 4, c = idx & 15;
            int m = m0 + r, e = k0 + c;
            As[c][r] = g_ao[(size_t)(((m >> 10) * 8 + (e >> 6)) * 1024 + (m & 1023)) * 64 + (e & 63)];
            Bs[c][r] = Wo[(size_t)(n0 + r) * E_ + e];
        }
        __syncthreads();
#pragma unroll
        for (int kk = 0; kk < 16; kk++) {
            float a[8];
#pragma unroll
            for (int i = 0; i < 8; i++) a[i] = As[kk][ty * 8 + i];
            float4 b0 = *(const float4*)&Bs[kk][tx * 8];
            float4 b1 = *(const float4*)&Bs[kk][tx * 8 + 4];
            float b[8] = {b0.x, b0.y, b0.z, b0.w, b1.x, b1.y, b1.z, b1.w};
#pragma unroll
            for (int i = 0; i < 8; i++)
#pragma unroll
                for (int j = 0; j < 8; j++) acc[i][j] += a[i] * b[j];
        }
        __syncthreads();
    }
#pragma unroll
    for (int i = 0; i < 8; i++) {
        int m = m0 + ty * 8 + i;
#pragma unroll
        for (int j = 0; j < 8; j++) {
            int n = n0 + tx * 8 + j;
            out[(size_t)m * 512 + n] = acc[i][j] + bo[n];
        }
    }
}

// ----------------------------------------------------------------- launcher
extern "C" void kernel_launch(void* const* d_in, const int* in_sizes, int n_in,
                              void* d_out, int out_size) {
    const float* x     = (const float*)d_in[0];
    const float* gamma = (const float*)d_in[2];
    const float* beta  = (const float*)d_in[3];
    const float* Wq    = (const float*)d_in[4];
    const float* bq    = (const float*)d_in[5];
    const float* Wk    = (const float*)d_in[6];
    const float* bk    = (const float*)d_in[7];
    const float* Wv    = (const float*)d_in[8];
    const float* bv    = (const float*)d_in[9];
    const float* Wo    = (const float*)d_in[10];
    const float* bo    = (const float*)d_in[11];
    const float* Er    = (const float*)d_in[12];
    float* out = (float*)d_out;

    ln_kernel<<<M_, 128>>>(x, gamma, beta);
    qkv_kernel<<<dim3(12, 64), 256>>>(Wq, bq, Wk, bk, Wv, bv);
    qk_kernel<<<dim3(8, 8, BH_), 256>>>();
    qer_kernel<<<dim3(8, 8, BH_), 256>>>(Er);
    softmax_kernel<<<dim3(L_, BH_), 128>>>();
    pv_kernel<<<dim3(8, BH_), 128>>>();
    oproj_kernel<<<dim3(4, 64), 256>>>(Wo, bo, out);
}